// round 15
// baseline (speedup 1.0000x reference)
#include <cuda_runtime.h>
#include <cuda_bf16.h>
#include <cstdint>
#include <cstddef>
#include <math.h>

// Problem constants
constexpr int B_   = 4;
constexpr int N_   = 744;
constexpr int H_   = 8;
constexpr int W_   = 128;
constexpr int C3_  = 3 * H_ * W_;   // 3072
constexpr int BN_  = B_ * N_;       // 2976
constexpr int BH_  = B_ * H_;       // 32
constexpr int NT64 = 12;            // 64-wide tiles over padded n
constexpr int NP_  = 768;           // padded n

// Scratch (device globals -- no allocations allowed)
__device__ __nv_bfloat16 g_qvh[(size_t)BN_ * C3_];        // q/vf/vb in bf16
__device__ __nv_bfloat16 g_Ebf[(size_t)BH_ * NP_ * NP_];  // exp(l) bf16 padded
__device__ unsigned int g_q8[(size_t)BH_ * NP_ * 32];     // q quantized u8 (4/word)
__device__ unsigned int g_k8[(size_t)BH_ * NP_ * 32];     // x*wk quantized u8
__device__ float g_denpart[(size_t)NT64 * BH_ * N_];
__device__ float g_rden[(size_t)BH_ * N_];
__device__ __nv_bfloat16 g_vbb[(size_t)BH_ * NP_ * W_];   // vb*rden bf16 padded
__device__ __nv_bfloat16 g_yhh[(size_t)H_ * BN_ * W_];    // per-head y, bf16

// ---------------------------------------------------------------------------
// mma / ldmatrix / sad helpers
// ---------------------------------------------------------------------------
__device__ __forceinline__ void ldsm4(unsigned int* r, unsigned int saddr) {
    asm volatile("ldmatrix.sync.aligned.m8n8.x4.shared.b16 {%0,%1,%2,%3}, [%4];"
        : "=r"(r[0]), "=r"(r[1]), "=r"(r[2]), "=r"(r[3]) : "r"(saddr));
}

__device__ __forceinline__ void ldsm4t(unsigned int* r, unsigned int saddr) {
    asm volatile("ldmatrix.sync.aligned.m8n8.x4.trans.shared.b16 {%0,%1,%2,%3}, [%4];"
        : "=r"(r[0]), "=r"(r[1]), "=r"(r[2]), "=r"(r[3]) : "r"(saddr));
}

__device__ __forceinline__ void mma16816(float* d, const unsigned int* a,
                                         unsigned int b0, unsigned int b1) {
    asm volatile(
        "mma.sync.aligned.m16n8k16.row.col.f32.bf16.bf16.f32 "
        "{%0,%1,%2,%3}, {%4,%5,%6,%7}, {%8,%9}, {%0,%1,%2,%3};"
        : "+f"(d[0]), "+f"(d[1]), "+f"(d[2]), "+f"(d[3])
        : "r"(a[0]), "r"(a[1]), "r"(a[2]), "r"(a[3]), "r"(b0), "r"(b1));
}

// Sum of 4 byte abs-diffs, accumulated: d = c + sum_i |a_i - b_i|
__device__ __forceinline__ unsigned int sad4(unsigned int a, unsigned int b,
                                             unsigned int c) {
    unsigned int d;
    asm("vabsdiff4.u32.u32.u32.add %0, %1, %2, %3;"
        : "=r"(d) : "r"(a), "r"(b), "r"(c));
    return d;
}

// Quantize 4 floats to biased-u8 (LSB = 0.004) packed into one uint
__device__ __forceinline__ unsigned int quant4(float4 f) {
    int a = __float2int_rn(f.x * 250.f) + 128;
    int b = __float2int_rn(f.y * 250.f) + 128;
    int c = __float2int_rn(f.z * 250.f) + 128;
    int d = __float2int_rn(f.w * 250.f) + 128;
    a = max(0, min(255, a));
    b = max(0, min(255, b));
    c = max(0, min(255, c));
    d = max(0, min(255, d));
    return (unsigned int)a | ((unsigned int)b << 8) |
           ((unsigned int)c << 16) | ((unsigned int)d << 24);
}

__device__ __forceinline__ uint4 pack8_bf16(float4 a, float4 b) {
    __nv_bfloat162 p0 = __floats2bfloat162_rn(a.x, a.y);
    __nv_bfloat162 p1 = __floats2bfloat162_rn(a.z, a.w);
    __nv_bfloat162 p2 = __floats2bfloat162_rn(b.x, b.y);
    __nv_bfloat162 p3 = __floats2bfloat162_rn(b.z, b.w);
    uint4 u;
    u.x = *(unsigned int*)&p0;
    u.y = *(unsigned int*)&p1;
    u.z = *(unsigned int*)&p2;
    u.w = *(unsigned int*)&p3;
    return u;
}

// ---------------------------------------------------------------------------
// K1: qv = x @ wqv_w^T + bias -> bf16  (2976 x 3072 x 128), tensor cores.
// CTA 128m x 128n, 8 warps (4m x 2n), warp tile 32m x 64n, K chunks of 64.
// ---------------------------------------------------------------------------
__global__ void __launch_bounds__(256) k_qv_mma(const float* __restrict__ x,
                                               const float* __restrict__ wq,
                                               const float* __restrict__ bias) {
    __shared__ __align__(16) unsigned char smem[32768];
    const int A_OFF = 0;       // 128 x 64 bf16 (k-major, swizzled)
    const int B_OFF = 16384;   // 128 x 64 bf16
    int m0 = blockIdx.y * 128;
    int n0 = blockIdx.x * 128;
    int tid = threadIdx.x;
    int lane = tid & 31;
    int wid = tid >> 5;
    int mw = (wid >> 1) * 32;
    int nw = (wid & 1) * 64;
    unsigned int sbase = (unsigned int)__cvta_generic_to_shared(smem);
    float acc[2][8][4] = {};
    for (int kc = 0; kc < 128; kc += 64) {
        if (kc != 0) __syncthreads();
#pragma unroll
        for (int l = 0; l < 4; l++) {
            int e = tid + l * 256;
            int row = e >> 3;
            int ch = e & 7;
            int sw = ch ^ (row & 7);
            int gm = m0 + row;
            float4 a0 = make_float4(0.f, 0.f, 0.f, 0.f);
            float4 a1 = make_float4(0.f, 0.f, 0.f, 0.f);
            if (gm < BN_) {
                const float* src = x + (size_t)gm * 128 + kc + ch * 8;
                a0 = *(const float4*)src;
                a1 = *(const float4*)(src + 4);
            }
            *(uint4*)(smem + A_OFF + 16 * (row * 8 + sw)) = pack8_bf16(a0, a1);
            const float* srcb = wq + (size_t)(n0 + row) * 128 + kc + ch * 8;
            float4 b0 = *(const float4*)srcb;
            float4 b1 = *(const float4*)(srcb + 4);
            *(uint4*)(smem + B_OFF + 16 * (row * 8 + sw)) = pack8_bf16(b0, b1);
        }
        __syncthreads();
#pragma unroll
        for (int ks = 0; ks < 4; ks++) {
            int chb = 2 * ks + (lane >> 4);
            unsigned int afr[2][4];
#pragma unroll
            for (int ms = 0; ms < 2; ms++) {
                int row = mw + ms * 16 + (lane & 15);
                ldsm4(afr[ms], sbase + A_OFF + 16 * (row * 8 + (chb ^ (row & 7))));
            }
#pragma unroll
            for (int nsp = 0; nsp < 4; nsp++) {
                unsigned int bfr[4];
                int row = nw + nsp * 16 + (lane & 15);
                ldsm4(bfr, sbase + B_OFF + 16 * (row * 8 + (chb ^ (row & 7))));
#pragma unroll
                for (int ms = 0; ms < 2; ms++) {
                    mma16816(acc[ms][nsp * 2], afr[ms], bfr[0], bfr[2]);
                    mma16816(acc[ms][nsp * 2 + 1], afr[ms], bfr[1], bfr[3]);
                }
            }
        }
    }
#pragma unroll
    for (int ms = 0; ms < 2; ms++) {
        int gm0 = m0 + mw + ms * 16 + (lane >> 2);
        int gm1 = gm0 + 8;
#pragma unroll
        for (int ns = 0; ns < 8; ns++) {
            int col = n0 + nw + ns * 8 + (lane & 3) * 2;
            float2 bv = *(const float2*)&bias[col];
            if (gm0 < BN_) {
                __nv_bfloat162 o = __floats2bfloat162_rn(acc[ms][ns][0] + bv.x,
                                                         acc[ms][ns][1] + bv.y);
                *(__nv_bfloat162*)&g_qvh[(size_t)gm0 * C3_ + col] = o;
            }
            if (gm1 < BN_) {
                __nv_bfloat162 o = __floats2bfloat162_rn(acc[ms][ns][2] + bv.x,
                                                         acc[ms][ns][3] + bv.y);
                *(__nv_bfloat162*)&g_qvh[(size_t)gm1 * C3_ + col] = o;
            }
        }
    }
}

// ---------------------------------------------------------------------------
// K1b: quantize q (from g_qvh) and k = x*wk to biased-u8, once per (bh, s).
// ---------------------------------------------------------------------------
__global__ void __launch_bounds__(256) k_quant(const float* __restrict__ x,
                                               const float* __restrict__ wk) {
    int idx = blockIdx.x * 256 + threadIdx.x;   // BH_*NP_*32 total
    int p = idx & 31;                           // pack: w = p*4..p*4+3
    int rest = idx >> 5;
    int s = rest % NP_;
    int bh = rest / NP_;
    if (bh >= BH_) return;
    int b = bh >> 3, h = bh & 7;
    unsigned int qu = 0x80808080u;
    unsigned int ku = 0x80808080u;
    if (s < N_) {
        uint2 u2 = *(const uint2*)(g_qvh + (size_t)(b * N_ + s) * C3_ + h * 128 + p * 4);
        __nv_bfloat162 h0 = *(__nv_bfloat162*)&u2.x;
        __nv_bfloat162 h1 = *(__nv_bfloat162*)&u2.y;
        float4 qf = make_float4(__low2float(h0), __high2float(h0),
                                __low2float(h1), __high2float(h1));
        qu = quant4(qf);
        float4 xv = *(const float4*)&x[((size_t)(b * N_ + s)) * 128 + p * 4];
        float4 wv = *(const float4*)&wk[h * 128 + p * 4];
        float4 kf;
        kf.x = xv.x * wv.x;
        kf.y = xv.y * wv.y;
        kf.z = xv.z * wv.z;
        kf.w = xv.w * wv.w;
        ku = quant4(kf);
    }
    g_q8[((size_t)bh * NP_ + s) * 32 + p] = qu;
    g_k8[((size_t)bh * NP_ + s) * 32 + p] = ku;
}

// ---------------------------------------------------------------------------
// K2: E[i,j] = exp(-scale * sad(q8[i], k8[j])) -> bf16 padded.
//     64x64 CTA tile, 4x4 outputs per thread. Fill = pure uint4 copies.
// ---------------------------------------------------------------------------
__global__ void __launch_bounds__(256) k_scores() {
    __shared__ unsigned int q_sh[64][32];   // 4 bytes/cell, chunk-XOR swizzled
    __shared__ unsigned int k_sh[64][32];
    __shared__ float part[16][64];
    int bh = blockIdx.z;
    int i0 = blockIdx.y * 64, j0 = blockIdx.x * 64;
    int tid = threadIdx.x;
    int cg = tid & 15, rg = tid >> 4;
    const unsigned int* q8 = g_q8 + (size_t)bh * NP_ * 32;
    const unsigned int* k8 = g_k8 + (size_t)bh * NP_ * 32;
#pragma unroll
    for (int l = 0; l < 4; l++) {
        int e = tid + l * 256;              // 0..1023
        int v = e & 511;
        int row = v >> 3;
        int ch = v & 7;
        int sw = ch ^ ((row >> 2) & 7);
        if (e < 512) {
            uint4 u = *(const uint4*)(q8 + ((size_t)(i0 + row)) * 32 + ch * 4);
            *(uint4*)&q_sh[row][sw * 4] = u;
        } else {
            uint4 u = *(const uint4*)(k8 + ((size_t)(j0 + row)) * 32 + ch * 4);
            *(uint4*)&k_sh[row][sw * 4] = u;
        }
    }
    __syncthreads();
    unsigned int acc[4][4];
#pragma unroll
    for (int i = 0; i < 4; i++) {
#pragma unroll
        for (int j = 0; j < 4; j++) acc[i][j] = 0u;
    }
#pragma unroll
    for (int p4 = 0; p4 < 8; p4++) {        // 16 w per iteration
        uint4 qv[4];
        uint4 kv[4];
#pragma unroll
        for (int i = 0; i < 4; i++) {
            int row = rg * 4 + i;
            int ch = p4 ^ ((row >> 2) & 7);
            qv[i] = *(const uint4*)&q_sh[row][ch * 4];
        }
#pragma unroll
        for (int j = 0; j < 4; j++) {
            int row = cg * 4 + j;
            int ch = p4 ^ ((row >> 2) & 7);
            kv[j] = *(const uint4*)&k_sh[row][ch * 4];
        }
#pragma unroll
        for (int i = 0; i < 4; i++) {
#pragma unroll
            for (int j = 0; j < 4; j++) {
                unsigned int a = acc[i][j];
                a = sad4(qv[i].x, kv[j].x, a);
                a = sad4(qv[i].y, kv[j].y, a);
                a = sad4(qv[i].z, kv[j].z, a);
                a = sad4(qv[i].w, kv[j].w, a);
                acc[i][j] = a;
            }
        }
    }
    const float nfac = -3.5355339059e-4f;   // -(1/sqrt(128)) * 0.004
    float csum[4] = {0.f, 0.f, 0.f, 0.f};
    __nv_bfloat16* Erow = g_Ebf + (size_t)bh * NP_ * NP_;
    int jc0 = j0 + cg * 4;
    bool cv = (jc0 < N_);                   // 744 % 4 == 0: all-or-nothing
#pragma unroll
    for (int i = 0; i < 4; i++) {
        int gi = i0 + rg * 4 + i;
        bool valid = (gi < N_) && cv;
        float ev[4];
#pragma unroll
        for (int j = 0; j < 4; j++) {
            ev[j] = valid ? __expf(nfac * (float)acc[i][j]) : 0.f;
        }
        __nv_bfloat162 p0 = __floats2bfloat162_rn(ev[0], ev[1]);
        __nv_bfloat162 p1 = __floats2bfloat162_rn(ev[2], ev[3]);
        uint2 u;
        u.x = *(unsigned int*)&p0;
        u.y = *(unsigned int*)&p1;
        *(uint2*)&Erow[(size_t)gi * NP_ + jc0] = u;
        if (valid) {
#pragma unroll
            for (int j = 0; j < 4; j++) csum[j] += ev[j];
        }
    }
#pragma unroll
    for (int j = 0; j < 4; j++) part[rg][cg * 4 + j] = csum[j];
    __syncthreads();
    if (tid < 64) {
        int gj = j0 + tid;
        if (gj < N_) {
            float s = 0.f;
#pragma unroll
            for (int r = 0; r < 16; r++) s += part[r][tid];
            g_denpart[((size_t)blockIdx.y * BH_ + bh) * N_ + gj] = s;
        }
    }
}

// ---------------------------------------------------------------------------
// K3: fused rden + vb scaling.
//   rden = 1/(1 + sum_t denpart[t])  (computed redundantly per wp, broadcast
//   loads); wp==0 stores g_rden for k_av's epilogue.
//   g_vbb = vb * rden -> bf16, padded rows zero.
// ---------------------------------------------------------------------------
__global__ void __launch_bounds__(256) k_prep() {
    int idx = blockIdx.x * 256 + threadIdx.x;
    int wp = idx & 63;
    int rest = idx >> 6;
    int s = rest % NP_;
    int bh = rest / NP_;
    if (bh >= BH_) return;
    int b = bh >> 3, h = bh & 7;
    unsigned int ub = 0u;
    if (s < N_) {
        float sden = 0.f;
#pragma unroll
        for (int t = 0; t < NT64; t++) {
            sden += g_denpart[((size_t)t * BH_ + bh) * N_ + s];
        }
        float r = 1.f / (1.f + sden);
        if (wp == 0) {
            g_rden[bh * N_ + s] = r;
        }
        const __nv_bfloat16* vb = g_qvh + (size_t)(b * N_ + s) * C3_ + (16 + h) * 128 + wp * 2;
        unsigned int raw = *(const unsigned int*)vb;
        __nv_bfloat162 hv = *(__nv_bfloat162*)&raw;
        __nv_bfloat162 o = __floats2bfloat162_rn(__low2float(hv) * r,
                                                 __high2float(hv) * r);
        ub = *(unsigned int*)&o;
    }
    *(unsigned int*)&g_vbb[((size_t)bh * NP_ + s) * W_ + wp * 2] = ub;
}

// ---------------------------------------------------------------------------
// K4: tensor-core attention apply.
//   acc1 = E^T @ vf  (scaled by rden[d] at epilogue)
//   acc2 = E @ (vb*rden[s])
// CTA: 64 d x 128 w, 8 warps (4 d-subtiles x 2 w-halves), s-chunks of 64.
// Loader is pure uint4 copies (no conversion on the producer path).
// ---------------------------------------------------------------------------
__global__ void __launch_bounds__(256) k_av_mma() {
    __shared__ __align__(16) unsigned char smem[49152];
    const int ETR_OFF = 0;       // E^T source: [s][d] 64x64 bf16
    const int ED_OFF  = 8192;    // E source:   [d][s] 64x64 bf16
    const int VF_OFF  = 16384;   // vf: [s][w] 64x128 bf16
    const int VB_OFF  = 32768;   // vb*rden: [s][w] 64x128 bf16

    int d0 = blockIdx.x * 64;
    int b = blockIdx.y;
    int h = blockIdx.z;
    int bh = b * 8 + h;
    int tid = threadIdx.x;
    int lane = tid & 31;
    int wid = tid >> 5;
    int dw = (wid >> 1) * 16;   // warp d-subtile base (0/16/32/48)
    int n0 = (wid & 1) * 64;    // warp w-half (0/64)

    const __nv_bfloat16* Ebase = g_Ebf + (size_t)bh * NP_ * NP_;
    const __nv_bfloat16* Vfp = g_qvh + (size_t)b * N_ * C3_ + (8 + h) * 128;
    const __nv_bfloat16* Vbp = g_vbb + (size_t)bh * NP_ * W_;

    unsigned int sbase = (unsigned int)__cvta_generic_to_shared(smem);

    float acc1[8][4];
    float acc2[8][4];
#pragma unroll
    for (int i = 0; i < 8; i++) {
#pragma unroll
        for (int j = 0; j < 4; j++) {
            acc1[i][j] = 0.f;
            acc2[i][j] = 0.f;
        }
    }

    for (int st = 0; st < NP_ / 64; st++) {
        int s0 = st * 64;
        uint4 re1[2];
        uint4 re2[2];
        uint4 rvf[4];
        uint4 rvb[4];
#pragma unroll
        for (int l = 0; l < 2; l++) {
            int v = tid + l * 256;
            int row = v >> 3;
            int ch = v & 7;
            re1[l] = *(const uint4*)(Ebase + (size_t)(s0 + row) * NP_ + d0 + ch * 8);
            re2[l] = *(const uint4*)(Ebase + (size_t)(d0 + row) * NP_ + s0 + ch * 8);
        }
#pragma unroll
        for (int l = 0; l < 4; l++) {
            int v = tid + l * 256;
            int row = v >> 4;
            int ch = v & 15;
            int gs = s0 + row;
            if (gs < N_) {
                rvf[l] = *(const uint4*)(Vfp + (size_t)gs * C3_ + ch * 8);
            } else {
                rvf[l] = make_uint4(0u, 0u, 0u, 0u);
            }
            rvb[l] = *(const uint4*)(Vbp + (size_t)gs * W_ + ch * 8);
        }
        __syncthreads();
#pragma unroll
        for (int l = 0; l < 2; l++) {
            int v = tid + l * 256;
            int row = v >> 3;
            int ch = v & 7;
            int sw = ch ^ (row & 7);
            *(uint4*)(smem + ETR_OFF + 16 * (row * 8 + sw)) = re1[l];
            *(uint4*)(smem + ED_OFF + 16 * (row * 8 + sw)) = re2[l];
        }
#pragma unroll
        for (int l = 0; l < 4; l++) {
            int v = tid + l * 256;
            int row = v >> 4;
            int ch = v & 15;
            int sw = ch ^ (row & 7);
            *(uint4*)(smem + VF_OFF + 16 * (row * 16 + sw)) = rvf[l];
            *(uint4*)(smem + VB_OFF + 16 * (row * 16 + sw)) = rvb[l];
        }
        __syncthreads();
#pragma unroll
        for (int ks = 0; ks < 4; ks++) {
            int k0 = ks * 16;
            unsigned int a1[4];
            unsigned int a2[4];
            // A1 = E^T fragment via trans-ldmatrix from [s][d] tile
            int srow = k0 + (lane & 7) + ((lane >> 4) & 1) * 8;
            int sch = (dw >> 3) + ((lane >> 3) & 1);
            ldsm4t(a1, sbase + ETR_OFF + 16 * (srow * 8 + (sch ^ (srow & 7))));
            // A2 = E fragment via ldmatrix from [d][s] tile
            int drow = dw + (lane & 15);
            int dch = (k0 >> 3) + (lane >> 4);
            ldsm4(a2, sbase + ED_OFF + 16 * (drow * 8 + (dch ^ (drow & 7))));
            // B fragments from [s][w] tiles (k-major -> trans)
            int krow = k0 + (lane & 7) + ((lane >> 3) & 1) * 8;
            int kx = krow & 7;
#pragma unroll
            for (int nt2 = 0; nt2 < 4; nt2++) {
                int ch = ((n0 + nt2 * 16) >> 3) + (lane >> 4);
                unsigned int rbf[4];
                unsigned int rbb[4];
                ldsm4t(rbf, sbase + VF_OFF + 16 * (krow * 16 + (ch ^ kx)));
                ldsm4t(rbb, sbase + VB_OFF + 16 * (krow * 16 + (ch ^ kx)));
                mma16816(acc1[nt2 * 2], a1, rbf[0], rbf[1]);
                mma16816(acc1[nt2 * 2 + 1], a1, rbf[2], rbf[3]);
                mma16816(acc2[nt2 * 2], a2, rbb[0], rbb[1]);
                mma16816(acc2[nt2 * 2 + 1], a2, rbb[2], rbb[3]);
            }
        }
    }
    // epilogue: y = rden[d]*acc1 + acc2  -> bf16
    int r0 = d0 + dw + (lane >> 2);
    int r1 = r0 + 8;
    const float* rden = g_rden + (size_t)bh * N_;
    float rd0 = (r0 < N_) ? rden[r0] : 0.f;
    float rd1 = (r1 < N_) ? rden[r1] : 0.f;
    __nv_bfloat16* yb = g_yhh + (size_t)h * BN_ * W_ + (size_t)b * N_ * W_;
#pragma unroll
    for (int nt = 0; nt < 8; nt++) {
        int col = n0 + nt * 8 + (lane & 3) * 2;
        if (r0 < N_) {
            __nv_bfloat162 o0 = __floats2bfloat162_rn(
                rd0 * acc1[nt][0] + acc2[nt][0],
                rd0 * acc1[nt][1] + acc2[nt][1]);
            *(__nv_bfloat162*)&yb[(size_t)r0 * W_ + col] = o0;
        }
        if (r1 < N_) {
            __nv_bfloat162 o1 = __floats2bfloat162_rn(
                rd1 * acc1[nt][2] + acc2[nt][2],
                rd1 * acc1[nt][3] + acc2[nt][3]);
            *(__nv_bfloat162*)&yb[(size_t)r1 * W_ + col] = o1;
        }
    }
}

// ---------------------------------------------------------------------------
// K5: y = sum_h y_h; y = qgelu(y + 4.5) - 4.5; out = x + y @ fanin_w^T + fb
// ---------------------------------------------------------------------------
__device__ __forceinline__ float qact(float v) {
    float z = v + 4.5f;
    return z / (1.f + __expf(-1.702f * z)) - 4.5f;
}

__global__ void __launch_bounds__(256) k_final(const float* __restrict__ x,
                                               const float* __restrict__ fw,
                                               const float* __restrict__ fbias,
                                               float* __restrict__ out) {
    __shared__ float ag[32][128];
    __shared__ float bt[128][33];
    int m0 = blockIdx.x * 32;
    int tid = threadIdx.x;
    int cq = tid & 31, rg = tid >> 5;
#pragma unroll
    for (int l = 0; l < 4; l++) {
        int e = tid + l * 256;
        int r = e >> 5;
        int wi = (e & 31) * 4;
        float4 s = make_float4(0.f, 0.f, 0.f, 0.f);
#pragma unroll
        for (int hh = 0; hh < H_; hh++) {
            uint2 u = *(const uint2*)&g_yhh[((size_t)hh * BN_ + m0 + r) * 128 + wi];
            __nv_bfloat162 h0 = *(__nv_bfloat162*)&u.x;
            __nv_bfloat162 h1 = *(__nv_bfloat162*)&u.y;
            s.x += __low2float(h0);
            s.y += __high2float(h0);
            s.z += __low2float(h1);
            s.w += __high2float(h1);
        }
        float4 a;
        a.x = qact(s.x); a.y = qact(s.y); a.z = qact(s.z); a.w = qact(s.w);
        *(float4*)&ag[r][wi] = a;
    }
    float acc[4][4] = {};
    for (int k0 = 0; k0 < 128; k0 += 32) {
#pragma unroll
        for (int l = 0; l < 16; l++) {
            int e = tid + l * 256;
            int c = e >> 5;
            int kk = e & 31;
            bt[c][kk] = fw[(size_t)c * 128 + k0 + kk];
        }
        __syncthreads();
#pragma unroll
        for (int kk = 0; kk < 32; kk++) {
            float av[4];
            float bv[4];
#pragma unroll
            for (int i = 0; i < 4; i++) av[i] = ag[rg * 4 + i][k0 + kk];
#pragma unroll
            for (int j = 0; j < 4; j++) bv[j] = bt[cq * 4 + j][kk];
#pragma unroll
            for (int i = 0; i < 4; i++) {
#pragma unroll
                for (int j = 0; j < 4; j++) {
                    acc[i][j] += av[i] * bv[j];
                }
            }
        }
        __syncthreads();
    }
    int c0 = cq * 4;
    float4 fb4 = *(const float4*)&fbias[c0];
#pragma unroll
    for (int i = 0; i < 4; i++) {
        int row = m0 + rg * 4 + i;   // BN_ = 93*32, exact fit
        float4 xr = *(const float4*)&x[(size_t)row * 128 + c0];
        float4 o;
        o.x = xr.x + acc[i][0] + fb4.x;
        o.y = xr.y + acc[i][1] + fb4.y;
        o.z = xr.z + acc[i][2] + fb4.z;
        o.w = xr.w + acc[i][3] + fb4.w;
        *(float4*)&out[(size_t)row * 128 + c0] = o;
    }
}

// ---------------------------------------------------------------------------
extern "C" void kernel_launch(void* const* d_in, const int* in_sizes, int n_in,
                              void* d_out, int out_size) {
    (void)in_sizes; (void)n_in; (void)out_size;
    const float* x       = (const float*)d_in[0];
    const float* wk      = (const float*)d_in[1];
    const float* wqv_w   = (const float*)d_in[2];
    const float* wqv_b   = (const float*)d_in[3];
    const float* fanin_w = (const float*)d_in[4];
    const float* fanin_b = (const float*)d_in[5];
    float* out = (float*)d_out;

    k_qv_mma<<<dim3(C3_ / 128, (BN_ + 127) / 128), 256>>>(x, wqv_w, wqv_b);
    k_quant<<<(BH_ * NP_ * 32) / 256, 256>>>(x, wk);
    k_scores<<<dim3(NT64, NT64, BH_), 256>>>();
    k_prep<<<(BH_ * NP_ * 64) / 256, 256>>>();
    k_av_mma<<<dim3(NP_ / 64, B_, H_), 256>>>();
    k_final<<<BN_ / 32, 256>>>(x, fanin_w, fanin_b, out);
}

// round 16
// speedup vs baseline: 1.1928x; 1.1928x over previous
#include <cuda_runtime.h>
#include <cuda_bf16.h>
#include <cstdint>
#include <cstddef>
#include <math.h>

// Problem constants
constexpr int B_   = 4;
constexpr int N_   = 744;
constexpr int H_   = 8;
constexpr int W_   = 128;
constexpr int C3_  = 3 * H_ * W_;   // 3072
constexpr int BN_  = B_ * N_;       // 2976
constexpr int BH_  = B_ * H_;       // 32
constexpr int NT64 = 12;            // 64-wide tiles over padded n
constexpr int NP_  = 768;           // padded n

// Scratch (device globals -- no allocations allowed)
__device__ __nv_bfloat16 g_qvh[(size_t)BN_ * C3_];        // q/vf/vb in bf16
__device__ __nv_bfloat16 g_Ebf[(size_t)BH_ * NP_ * NP_];  // exp(l) bf16 padded
__device__ unsigned int g_q8[(size_t)BH_ * NP_ * 32];     // q quantized u8 (4/word)
__device__ unsigned int g_k8[(size_t)BH_ * NP_ * 32];     // x*wk quantized u8
__device__ float g_denpart[(size_t)NT64 * BH_ * N_];
__device__ float g_rden[(size_t)BH_ * N_];
__device__ __nv_bfloat16 g_vbb[(size_t)BH_ * NP_ * W_];   // vb*rden bf16 padded
__device__ __nv_bfloat16 g_yhh[(size_t)H_ * BN_ * W_];    // per-head y, bf16

// ---------------------------------------------------------------------------
// mma / ldmatrix / sad / cp.async helpers
// ---------------------------------------------------------------------------
__device__ __forceinline__ void ldsm4(unsigned int* r, unsigned int saddr) {
    asm volatile("ldmatrix.sync.aligned.m8n8.x4.shared.b16 {%0,%1,%2,%3}, [%4];"
        : "=r"(r[0]), "=r"(r[1]), "=r"(r[2]), "=r"(r[3]) : "r"(saddr));
}

__device__ __forceinline__ void ldsm4t(unsigned int* r, unsigned int saddr) {
    asm volatile("ldmatrix.sync.aligned.m8n8.x4.trans.shared.b16 {%0,%1,%2,%3}, [%4];"
        : "=r"(r[0]), "=r"(r[1]), "=r"(r[2]), "=r"(r[3]) : "r"(saddr));
}

__device__ __forceinline__ void mma16816(float* d, const unsigned int* a,
                                         unsigned int b0, unsigned int b1) {
    asm volatile(
        "mma.sync.aligned.m16n8k16.row.col.f32.bf16.bf16.f32 "
        "{%0,%1,%2,%3}, {%4,%5,%6,%7}, {%8,%9}, {%0,%1,%2,%3};"
        : "+f"(d[0]), "+f"(d[1]), "+f"(d[2]), "+f"(d[3])
        : "r"(a[0]), "r"(a[1]), "r"(a[2]), "r"(a[3]), "r"(b0), "r"(b1));
}

__device__ __forceinline__ unsigned int sad4(unsigned int a, unsigned int b,
                                             unsigned int c) {
    unsigned int d;
    asm("vabsdiff4.u32.u32.u32.add %0, %1, %2, %3;"
        : "=r"(d) : "r"(a), "r"(b), "r"(c));
    return d;
}

__device__ __forceinline__ void cpa16(unsigned int dst, const void* src) {
    asm volatile("cp.async.cg.shared.global [%0], [%1], 16;"
        :: "r"(dst), "l"(src));
}

__device__ __forceinline__ void cpa16z(unsigned int dst, const void* src, int sz) {
    asm volatile("cp.async.cg.shared.global [%0], [%1], 16, %2;"
        :: "r"(dst), "l"(src), "r"(sz));
}

#define CP_COMMIT() asm volatile("cp.async.commit_group;")
#define CP_WAIT(n)  asm volatile("cp.async.wait_group %0;" :: "n"(n))

// Quantize 4 floats to biased-u8 (LSB = 0.004) packed into one uint
__device__ __forceinline__ unsigned int quant4(float4 f) {
    int a = __float2int_rn(f.x * 250.f) + 128;
    int b = __float2int_rn(f.y * 250.f) + 128;
    int c = __float2int_rn(f.z * 250.f) + 128;
    int d = __float2int_rn(f.w * 250.f) + 128;
    a = max(0, min(255, a));
    b = max(0, min(255, b));
    c = max(0, min(255, c));
    d = max(0, min(255, d));
    return (unsigned int)a | ((unsigned int)b << 8) |
           ((unsigned int)c << 16) | ((unsigned int)d << 24);
}

__device__ __forceinline__ uint4 pack8_bf16(float4 a, float4 b) {
    __nv_bfloat162 p0 = __floats2bfloat162_rn(a.x, a.y);
    __nv_bfloat162 p1 = __floats2bfloat162_rn(a.z, a.w);
    __nv_bfloat162 p2 = __floats2bfloat162_rn(b.x, b.y);
    __nv_bfloat162 p3 = __floats2bfloat162_rn(b.z, b.w);
    uint4 u;
    u.x = *(unsigned int*)&p0;
    u.y = *(unsigned int*)&p1;
    u.z = *(unsigned int*)&p2;
    u.w = *(unsigned int*)&p3;
    return u;
}

// ---------------------------------------------------------------------------
// K1: qv = x @ wqv_w^T + bias -> bf16  (2976 x 3072 x 128), tensor cores.
// ---------------------------------------------------------------------------
__global__ void __launch_bounds__(256) k_qv_mma(const float* __restrict__ x,
                                               const float* __restrict__ wq,
                                               const float* __restrict__ bias) {
    __shared__ __align__(16) unsigned char smem[32768];
    const int A_OFF = 0;
    const int B_OFF = 16384;
    int m0 = blockIdx.y * 128;
    int n0 = blockIdx.x * 128;
    int tid = threadIdx.x;
    int lane = tid & 31;
    int wid = tid >> 5;
    int mw = (wid >> 1) * 32;
    int nw = (wid & 1) * 64;
    unsigned int sbase = (unsigned int)__cvta_generic_to_shared(smem);
    float acc[2][8][4] = {};
    for (int kc = 0; kc < 128; kc += 64) {
        if (kc != 0) __syncthreads();
#pragma unroll
        for (int l = 0; l < 4; l++) {
            int e = tid + l * 256;
            int row = e >> 3;
            int ch = e & 7;
            int sw = ch ^ (row & 7);
            int gm = m0 + row;
            float4 a0 = make_float4(0.f, 0.f, 0.f, 0.f);
            float4 a1 = make_float4(0.f, 0.f, 0.f, 0.f);
            if (gm < BN_) {
                const float* src = x + (size_t)gm * 128 + kc + ch * 8;
                a0 = *(const float4*)src;
                a1 = *(const float4*)(src + 4);
            }
            *(uint4*)(smem + A_OFF + 16 * (row * 8 + sw)) = pack8_bf16(a0, a1);
            const float* srcb = wq + (size_t)(n0 + row) * 128 + kc + ch * 8;
            float4 b0 = *(const float4*)srcb;
            float4 b1 = *(const float4*)(srcb + 4);
            *(uint4*)(smem + B_OFF + 16 * (row * 8 + sw)) = pack8_bf16(b0, b1);
        }
        __syncthreads();
#pragma unroll
        for (int ks = 0; ks < 4; ks++) {
            int chb = 2 * ks + (lane >> 4);
            unsigned int afr[2][4];
#pragma unroll
            for (int ms = 0; ms < 2; ms++) {
                int row = mw + ms * 16 + (lane & 15);
                ldsm4(afr[ms], sbase + A_OFF + 16 * (row * 8 + (chb ^ (row & 7))));
            }
#pragma unroll
            for (int nsp = 0; nsp < 4; nsp++) {
                unsigned int bfr[4];
                int row = nw + nsp * 16 + (lane & 15);
                ldsm4(bfr, sbase + B_OFF + 16 * (row * 8 + (chb ^ (row & 7))));
#pragma unroll
                for (int ms = 0; ms < 2; ms++) {
                    mma16816(acc[ms][nsp * 2], afr[ms], bfr[0], bfr[2]);
                    mma16816(acc[ms][nsp * 2 + 1], afr[ms], bfr[1], bfr[3]);
                }
            }
        }
    }
#pragma unroll
    for (int ms = 0; ms < 2; ms++) {
        int gm0 = m0 + mw + ms * 16 + (lane >> 2);
        int gm1 = gm0 + 8;
#pragma unroll
        for (int ns = 0; ns < 8; ns++) {
            int col = n0 + nw + ns * 8 + (lane & 3) * 2;
            float2 bv = *(const float2*)&bias[col];
            if (gm0 < BN_) {
                __nv_bfloat162 o = __floats2bfloat162_rn(acc[ms][ns][0] + bv.x,
                                                         acc[ms][ns][1] + bv.y);
                *(__nv_bfloat162*)&g_qvh[(size_t)gm0 * C3_ + col] = o;
            }
            if (gm1 < BN_) {
                __nv_bfloat162 o = __floats2bfloat162_rn(acc[ms][ns][2] + bv.x,
                                                         acc[ms][ns][3] + bv.y);
                *(__nv_bfloat162*)&g_qvh[(size_t)gm1 * C3_ + col] = o;
            }
        }
    }
}

// ---------------------------------------------------------------------------
// K1b: quantize q (from g_qvh) and k = x*wk to biased-u8, once per (bh, s).
// ---------------------------------------------------------------------------
__global__ void __launch_bounds__(256) k_quant(const float* __restrict__ x,
                                               const float* __restrict__ wk) {
    int idx = blockIdx.x * 256 + threadIdx.x;
    int p = idx & 31;
    int rest = idx >> 5;
    int s = rest % NP_;
    int bh = rest / NP_;
    if (bh >= BH_) return;
    int b = bh >> 3, h = bh & 7;
    unsigned int qu = 0x80808080u;
    unsigned int ku = 0x80808080u;
    if (s < N_) {
        uint2 u2 = *(const uint2*)(g_qvh + (size_t)(b * N_ + s) * C3_ + h * 128 + p * 4);
        __nv_bfloat162 h0 = *(__nv_bfloat162*)&u2.x;
        __nv_bfloat162 h1 = *(__nv_bfloat162*)&u2.y;
        float4 qf = make_float4(__low2float(h0), __high2float(h0),
                                __low2float(h1), __high2float(h1));
        qu = quant4(qf);
        float4 xv = *(const float4*)&x[((size_t)(b * N_ + s)) * 128 + p * 4];
        float4 wv = *(const float4*)&wk[h * 128 + p * 4];
        float4 kf;
        kf.x = xv.x * wv.x;
        kf.y = xv.y * wv.y;
        kf.z = xv.z * wv.z;
        kf.w = xv.w * wv.w;
        ku = quant4(kf);
    }
    g_q8[((size_t)bh * NP_ + s) * 32 + p] = qu;
    g_k8[((size_t)bh * NP_ + s) * 32 + p] = ku;
}

// ---------------------------------------------------------------------------
// K2: E[i,j] = exp(-scale * sad(q8[i], k8[j])) -> bf16 padded.
// ---------------------------------------------------------------------------
__global__ void __launch_bounds__(256) k_scores() {
    __shared__ unsigned int q_sh[64][32];
    __shared__ unsigned int k_sh[64][32];
    __shared__ float part[16][64];
    int bh = blockIdx.z;
    int i0 = blockIdx.y * 64, j0 = blockIdx.x * 64;
    int tid = threadIdx.x;
    int cg = tid & 15, rg = tid >> 4;
    const unsigned int* q8 = g_q8 + (size_t)bh * NP_ * 32;
    const unsigned int* k8 = g_k8 + (size_t)bh * NP_ * 32;
#pragma unroll
    for (int l = 0; l < 4; l++) {
        int e = tid + l * 256;
        int v = e & 511;
        int row = v >> 3;
        int ch = v & 7;
        int sw = ch ^ ((row >> 2) & 7);
        if (e < 512) {
            uint4 u = *(const uint4*)(q8 + ((size_t)(i0 + row)) * 32 + ch * 4);
            *(uint4*)&q_sh[row][sw * 4] = u;
        } else {
            uint4 u = *(const uint4*)(k8 + ((size_t)(j0 + row)) * 32 + ch * 4);
            *(uint4*)&k_sh[row][sw * 4] = u;
        }
    }
    __syncthreads();
    unsigned int acc[4][4];
#pragma unroll
    for (int i = 0; i < 4; i++) {
#pragma unroll
        for (int j = 0; j < 4; j++) acc[i][j] = 0u;
    }
#pragma unroll
    for (int p4 = 0; p4 < 8; p4++) {
        uint4 qv[4];
        uint4 kv[4];
#pragma unroll
        for (int i = 0; i < 4; i++) {
            int row = rg * 4 + i;
            int ch = p4 ^ ((row >> 2) & 7);
            qv[i] = *(const uint4*)&q_sh[row][ch * 4];
        }
#pragma unroll
        for (int j = 0; j < 4; j++) {
            int row = cg * 4 + j;
            int ch = p4 ^ ((row >> 2) & 7);
            kv[j] = *(const uint4*)&k_sh[row][ch * 4];
        }
#pragma unroll
        for (int i = 0; i < 4; i++) {
#pragma unroll
            for (int j = 0; j < 4; j++) {
                unsigned int a = acc[i][j];
                a = sad4(qv[i].x, kv[j].x, a);
                a = sad4(qv[i].y, kv[j].y, a);
                a = sad4(qv[i].z, kv[j].z, a);
                a = sad4(qv[i].w, kv[j].w, a);
                acc[i][j] = a;
            }
        }
    }
    const float nfac = -3.5355339059e-4f;
    float csum[4] = {0.f, 0.f, 0.f, 0.f};
    __nv_bfloat16* Erow = g_Ebf + (size_t)bh * NP_ * NP_;
    int jc0 = j0 + cg * 4;
    bool cv = (jc0 < N_);
#pragma unroll
    for (int i = 0; i < 4; i++) {
        int gi = i0 + rg * 4 + i;
        bool valid = (gi < N_) && cv;
        float ev[4];
#pragma unroll
        for (int j = 0; j < 4; j++) {
            ev[j] = valid ? __expf(nfac * (float)acc[i][j]) : 0.f;
        }
        __nv_bfloat162 p0 = __floats2bfloat162_rn(ev[0], ev[1]);
        __nv_bfloat162 p1 = __floats2bfloat162_rn(ev[2], ev[3]);
        uint2 u;
        u.x = *(unsigned int*)&p0;
        u.y = *(unsigned int*)&p1;
        *(uint2*)&Erow[(size_t)gi * NP_ + jc0] = u;
        if (valid) {
#pragma unroll
            for (int j = 0; j < 4; j++) csum[j] += ev[j];
        }
    }
#pragma unroll
    for (int j = 0; j < 4; j++) part[rg][cg * 4 + j] = csum[j];
    __syncthreads();
    if (tid < 64) {
        int gj = j0 + tid;
        if (gj < N_) {
            float s = 0.f;
#pragma unroll
            for (int r = 0; r < 16; r++) s += part[r][tid];
            g_denpart[((size_t)blockIdx.y * BH_ + bh) * N_ + gj] = s;
        }
    }
}

// ---------------------------------------------------------------------------
// K3: reduce denominator partials -> rden = 1/(1 + colsum)
// ---------------------------------------------------------------------------
__global__ void k_rden() {
    int idx = blockIdx.x * blockDim.x + threadIdx.x;
    if (idx >= BH_ * N_) return;
    float s = 0.f;
#pragma unroll
    for (int t = 0; t < NT64; t++) {
        s += g_denpart[(size_t)t * BH_ * N_ + idx];
    }
    g_rden[idx] = 1.f / (1.f + s);
}

// ---------------------------------------------------------------------------
// K3b: vb*rden[s] -> bf16, padded rows zero
// ---------------------------------------------------------------------------
__global__ void __launch_bounds__(256) k_prep() {
    int idx = blockIdx.x * 256 + threadIdx.x;
    int wp = idx & 63;
    int rest = idx >> 6;
    int s = rest % NP_;
    int bh = rest / NP_;
    if (bh >= BH_) return;
    int b = bh >> 3, h = bh & 7;
    unsigned int ub = 0u;
    if (s < N_) {
        const __nv_bfloat16* vb = g_qvh + (size_t)(b * N_ + s) * C3_ + (16 + h) * 128 + wp * 2;
        unsigned int raw = *(const unsigned int*)vb;
        __nv_bfloat162 hv = *(__nv_bfloat162*)&raw;
        float r = g_rden[bh * N_ + s];
        __nv_bfloat162 o = __floats2bfloat162_rn(__low2float(hv) * r,
                                                 __high2float(hv) * r);
        ub = *(unsigned int*)&o;
    }
    *(unsigned int*)&g_vbb[((size_t)bh * NP_ + s) * W_ + wp * 2] = ub;
}

// ---------------------------------------------------------------------------
// K4: tensor-core attention apply, cp.async double-buffered pipeline.
//   acc1 = E^T @ vf  (scaled by rden[d] at epilogue)
//   acc2 = E @ (vb*rden[s])
// CTA: 64 d x 128 w, 8 warps, s-chunks of 64, 2-stage smem (2 x 48KB dynamic).
// ---------------------------------------------------------------------------
__device__ __forceinline__ void av_issue(unsigned int sb, int s0, int d0, int tid,
                                         const __nv_bfloat16* Ebase,
                                         const __nv_bfloat16* Vfp,
                                         const __nv_bfloat16* Vbp) {
    const int ETR_OFF = 0;
    const int ED_OFF  = 8192;
    const int VF_OFF  = 16384;
    const int VB_OFF  = 32768;
#pragma unroll
    for (int l = 0; l < 2; l++) {
        int v = tid + l * 256;
        int row = v >> 3;
        int ch = v & 7;
        int sw = ch ^ (row & 7);
        cpa16(sb + ETR_OFF + 16 * (row * 8 + sw),
              Ebase + (size_t)(s0 + row) * NP_ + d0 + ch * 8);
        cpa16(sb + ED_OFF + 16 * (row * 8 + sw),
              Ebase + (size_t)(d0 + row) * NP_ + s0 + ch * 8);
    }
#pragma unroll
    for (int l = 0; l < 4; l++) {
        int v = tid + l * 256;
        int row = v >> 4;
        int ch = v & 15;
        int sw = ch ^ (row & 7);
        int gs = s0 + row;
        int szf = (gs < N_) ? 16 : 0;
        cpa16z(sb + VF_OFF + 16 * (row * 16 + sw),
               Vfp + (size_t)gs * C3_ + ch * 8, szf);
        cpa16(sb + VB_OFF + 16 * (row * 16 + sw),
              Vbp + (size_t)gs * W_ + ch * 8);
    }
}

__global__ void __launch_bounds__(256) k_av_mma() {
    extern __shared__ __align__(16) unsigned char smem[];
    const int STAGE  = 49152;
    const int ETR_OFF = 0;
    const int ED_OFF  = 8192;
    const int VF_OFF  = 16384;
    const int VB_OFF  = 32768;

    int d0 = blockIdx.x * 64;
    int b = blockIdx.y;
    int h = blockIdx.z;
    int bh = b * 8 + h;
    int tid = threadIdx.x;
    int lane = tid & 31;
    int wid = tid >> 5;
    int dw = (wid >> 1) * 16;
    int n0 = (wid & 1) * 64;

    const __nv_bfloat16* Ebase = g_Ebf + (size_t)bh * NP_ * NP_;
    const __nv_bfloat16* Vfp = g_qvh + (size_t)b * N_ * C3_ + (8 + h) * 128;
    const __nv_bfloat16* Vbp = g_vbb + (size_t)bh * NP_ * W_;

    unsigned int sbase = (unsigned int)__cvta_generic_to_shared(smem);

    float acc1[8][4];
    float acc2[8][4];
#pragma unroll
    for (int i = 0; i < 8; i++) {
#pragma unroll
        for (int j = 0; j < 4; j++) {
            acc1[i][j] = 0.f;
            acc2[i][j] = 0.f;
        }
    }

    // prologue: chunk 0 into stage 0
    av_issue(sbase, 0, d0, tid, Ebase, Vfp, Vbp);
    CP_COMMIT();

    for (int st = 0; st < NP_ / 64; st++) {
        unsigned int sb = sbase + (unsigned int)(st & 1) * STAGE;
        if (st + 1 < NP_ / 64) {
            av_issue(sbase + (unsigned int)((st + 1) & 1) * STAGE,
                     (st + 1) * 64, d0, tid, Ebase, Vfp, Vbp);
            CP_COMMIT();
            CP_WAIT(1);
        } else {
            CP_WAIT(0);
        }
        __syncthreads();
#pragma unroll
        for (int ks = 0; ks < 4; ks++) {
            int k0 = ks * 16;
            unsigned int a1[4];
            unsigned int a2[4];
            int srow = k0 + (lane & 7) + ((lane >> 4) & 1) * 8;
            int sch = (dw >> 3) + ((lane >> 3) & 1);
            ldsm4t(a1, sb + ETR_OFF + 16 * (srow * 8 + (sch ^ (srow & 7))));
            int drow = dw + (lane & 15);
            int dch = (k0 >> 3) + (lane >> 4);
            ldsm4(a2, sb + ED_OFF + 16 * (drow * 8 + (dch ^ (drow & 7))));
            int krow = k0 + (lane & 7) + ((lane >> 3) & 1) * 8;
            int kx = krow & 7;
#pragma unroll
            for (int nt2 = 0; nt2 < 4; nt2++) {
                int ch = ((n0 + nt2 * 16) >> 3) + (lane >> 4);
                unsigned int rbf[4];
                unsigned int rbb[4];
                ldsm4t(rbf, sb + VF_OFF + 16 * (krow * 16 + (ch ^ kx)));
                ldsm4t(rbb, sb + VB_OFF + 16 * (krow * 16 + (ch ^ kx)));
                mma16816(acc1[nt2 * 2], a1, rbf[0], rbf[1]);
                mma16816(acc1[nt2 * 2 + 1], a1, rbf[2], rbf[3]);
                mma16816(acc2[nt2 * 2], a2, rbb[0], rbb[1]);
                mma16816(acc2[nt2 * 2 + 1], a2, rbb[2], rbb[3]);
            }
        }
        __syncthreads();
    }
    // epilogue: y = rden[d]*acc1 + acc2  -> bf16
    int r0 = d0 + dw + (lane >> 2);
    int r1 = r0 + 8;
    const float* rden = g_rden + (size_t)bh * N_;
    float rd0 = (r0 < N_) ? rden[r0] : 0.f;
    float rd1 = (r1 < N_) ? rden[r1] : 0.f;
    __nv_bfloat16* yb = g_yhh + (size_t)h * BN_ * W_ + (size_t)b * N_ * W_;
#pragma unroll
    for (int nt = 0; nt < 8; nt++) {
        int col = n0 + nt * 8 + (lane & 3) * 2;
        if (r0 < N_) {
            __nv_bfloat162 o0 = __floats2bfloat162_rn(
                rd0 * acc1[nt][0] + acc2[nt][0],
                rd0 * acc1[nt][1] + acc2[nt][1]);
            *(__nv_bfloat162*)&yb[(size_t)r0 * W_ + col] = o0;
        }
        if (r1 < N_) {
            __nv_bfloat162 o1 = __floats2bfloat162_rn(
                rd1 * acc1[nt][2] + acc2[nt][2],
                rd1 * acc1[nt][3] + acc2[nt][3]);
            *(__nv_bfloat162*)&yb[(size_t)r1 * W_ + col] = o1;
        }
    }
}

// ---------------------------------------------------------------------------
// K5: y = sum_h y_h; y = qgelu(y + 4.5) - 4.5; out = x + y @ fanin_w^T + fb
// ---------------------------------------------------------------------------
__device__ __forceinline__ float qact(float v) {
    float z = v + 4.5f;
    return z / (1.f + __expf(-1.702f * z)) - 4.5f;
}

__global__ void __launch_bounds__(256) k_final(const float* __restrict__ x,
                                               const float* __restrict__ fw,
                                               const float* __restrict__ fbias,
                                               float* __restrict__ out) {
    __shared__ float ag[32][128];
    __shared__ float bt[128][33];
    int m0 = blockIdx.x * 32;
    int tid = threadIdx.x;
    int cq = tid & 31, rg = tid >> 5;
#pragma unroll
    for (int l = 0; l < 4; l++) {
        int e = tid + l * 256;
        int r = e >> 5;
        int wi = (e & 31) * 4;
        float4 s = make_float4(0.f, 0.f, 0.f, 0.f);
#pragma unroll
        for (int hh = 0; hh < H_; hh++) {
            uint2 u = *(const uint2*)&g_yhh[((size_t)hh * BN_ + m0 + r) * 128 + wi];
            __nv_bfloat162 h0 = *(__nv_bfloat162*)&u.x;
            __nv_bfloat162 h1 = *(__nv_bfloat162*)&u.y;
            s.x += __low2float(h0);
            s.y += __high2float(h0);
            s.z += __low2float(h1);
            s.w += __high2float(h1);
        }
        float4 a;
        a.x = qact(s.x); a.y = qact(s.y); a.z = qact(s.z); a.w = qact(s.w);
        *(float4*)&ag[r][wi] = a;
    }
    float acc[4][4] = {};
    for (int k0 = 0; k0 < 128; k0 += 32) {
#pragma unroll
        for (int l = 0; l < 16; l++) {
            int e = tid + l * 256;
            int c = e >> 5;
            int kk = e & 31;
            bt[c][kk] = fw[(size_t)c * 128 + k0 + kk];
        }
        __syncthreads();
#pragma unroll
        for (int kk = 0; kk < 32; kk++) {
            float av[4];
            float bv[4];
#pragma unroll
            for (int i = 0; i < 4; i++) av[i] = ag[rg * 4 + i][k0 + kk];
#pragma unroll
            for (int j = 0; j < 4; j++) bv[j] = bt[cq * 4 + j][kk];
#pragma unroll
            for (int i = 0; i < 4; i++) {
#pragma unroll
                for (int j = 0; j < 4; j++) {
                    acc[i][j] += av[i] * bv[j];
                }
            }
        }
        __syncthreads();
    }
    int c0 = cq * 4;
    float4 fb4 = *(const float4*)&fbias[c0];
#pragma unroll
    for (int i = 0; i < 4; i++) {
        int row = m0 + rg * 4 + i;
        float4 xr = *(const float4*)&x[(size_t)row * 128 + c0];
        float4 o;
        o.x = xr.x + acc[i][0] + fb4.x;
        o.y = xr.y + acc[i][1] + fb4.y;
        o.z = xr.z + acc[i][2] + fb4.z;
        o.w = xr.w + acc[i][3] + fb4.w;
        *(float4*)&out[(size_t)row * 128 + c0] = o;
    }
}

// ---------------------------------------------------------------------------
extern "C" void kernel_launch(void* const* d_in, const int* in_sizes, int n_in,
                              void* d_out, int out_size) {
    (void)in_sizes; (void)n_in; (void)out_size;
    const float* x       = (const float*)d_in[0];
    const float* wk      = (const float*)d_in[1];
    const float* wqv_w   = (const float*)d_in[2];
    const float* wqv_b   = (const float*)d_in[3];
    const float* fanin_w = (const float*)d_in[4];
    const float* fanin_b = (const float*)d_in[5];
    float* out = (float*)d_out;

    cudaFuncSetAttribute(k_av_mma,
                         cudaFuncAttributeMaxDynamicSharedMemorySize, 98304);

    k_qv_mma<<<dim3(C3_ / 128, (BN_ + 127) / 128), 256>>>(x, wqv_w, wqv_b);
    k_quant<<<(BH_ * NP_ * 32) / 256, 256>>>(x, wk);
    k_scores<<<dim3(NT64, NT64, BH_), 256>>>();
    k_rden<<<(BH_ * N_ + 255) / 256, 256>>>();
    k_prep<<<(BH_ * NP_ * 64) / 256, 256>>>();
    k_av_mma<<<dim3(NP_ / 64, B_, H_), 256, 98304>>>();
    k_final<<<BN_ / 32, 256>>>(x, fanin_w, fanin_b, out);
}

// round 17
// speedup vs baseline: 1.1978x; 1.0042x over previous
#include <cuda_runtime.h>
#include <cuda_bf16.h>
#include <cstdint>
#include <cstddef>
#include <math.h>

// Problem constants
constexpr int B_   = 4;
constexpr int N_   = 744;
constexpr int H_   = 8;
constexpr int W_   = 128;
constexpr int C3_  = 3 * H_ * W_;   // 3072
constexpr int BN_  = B_ * N_;       // 2976
constexpr int BH_  = B_ * H_;       // 32
constexpr int NT64 = 12;            // 64-wide tiles over padded n
constexpr int NP_  = 768;           // padded n

// Scratch (device globals -- no allocations allowed)
__device__ __nv_bfloat16 g_qvh[(size_t)BN_ * C3_];        // q/vf/vb in bf16
__device__ __nv_bfloat16 g_Ebf[(size_t)BH_ * NP_ * NP_];  // exp(l) bf16 padded
__device__ unsigned int g_q8[(size_t)BH_ * NP_ * 32];     // q quantized u8 (4/word)
__device__ unsigned int g_k8[(size_t)BH_ * NP_ * 32];     // x*wk quantized u8
__device__ float g_denpart[(size_t)NT64 * BH_ * N_];
__device__ float g_rden[(size_t)BH_ * N_];
__device__ __nv_bfloat16 g_vbb[(size_t)BH_ * NP_ * W_];   // vb*rden bf16 padded
__device__ __nv_bfloat16 g_yhh[(size_t)H_ * BN_ * W_];    // per-head y, bf16

// ---------------------------------------------------------------------------
// mma / ldmatrix / sad / cp.async helpers
// ---------------------------------------------------------------------------
__device__ __forceinline__ void ldsm4(unsigned int* r, unsigned int saddr) {
    asm volatile("ldmatrix.sync.aligned.m8n8.x4.shared.b16 {%0,%1,%2,%3}, [%4];"
        : "=r"(r[0]), "=r"(r[1]), "=r"(r[2]), "=r"(r[3]) : "r"(saddr));
}

__device__ __forceinline__ void ldsm4t(unsigned int* r, unsigned int saddr) {
    asm volatile("ldmatrix.sync.aligned.m8n8.x4.trans.shared.b16 {%0,%1,%2,%3}, [%4];"
        : "=r"(r[0]), "=r"(r[1]), "=r"(r[2]), "=r"(r[3]) : "r"(saddr));
}

__device__ __forceinline__ void mma16816(float* d, const unsigned int* a,
                                         unsigned int b0, unsigned int b1) {
    asm volatile(
        "mma.sync.aligned.m16n8k16.row.col.f32.bf16.bf16.f32 "
        "{%0,%1,%2,%3}, {%4,%5,%6,%7}, {%8,%9}, {%0,%1,%2,%3};"
        : "+f"(d[0]), "+f"(d[1]), "+f"(d[2]), "+f"(d[3])
        : "r"(a[0]), "r"(a[1]), "r"(a[2]), "r"(a[3]), "r"(b0), "r"(b1));
}

__device__ __forceinline__ unsigned int sad4(unsigned int a, unsigned int b,
                                             unsigned int c) {
    unsigned int d;
    asm("vabsdiff4.u32.u32.u32.add %0, %1, %2, %3;"
        : "=r"(d) : "r"(a), "r"(b), "r"(c));
    return d;
}

__device__ __forceinline__ void cpa16(unsigned int dst, const void* src) {
    asm volatile("cp.async.cg.shared.global [%0], [%1], 16;"
        :: "r"(dst), "l"(src));
}

__device__ __forceinline__ void cpa16z(unsigned int dst, const void* src, int sz) {
    asm volatile("cp.async.cg.shared.global [%0], [%1], 16, %2;"
        :: "r"(dst), "l"(src), "r"(sz));
}

#define CP_COMMIT() asm volatile("cp.async.commit_group;")
#define CP_WAIT(n)  asm volatile("cp.async.wait_group %0;" :: "n"(n))

// Quantize 4 floats to biased-u8 (LSB = 0.004) packed into one uint
__device__ __forceinline__ unsigned int quant4(float4 f) {
    int a = __float2int_rn(f.x * 250.f) + 128;
    int b = __float2int_rn(f.y * 250.f) + 128;
    int c = __float2int_rn(f.z * 250.f) + 128;
    int d = __float2int_rn(f.w * 250.f) + 128;
    a = max(0, min(255, a));
    b = max(0, min(255, b));
    c = max(0, min(255, c));
    d = max(0, min(255, d));
    return (unsigned int)a | ((unsigned int)b << 8) |
           ((unsigned int)c << 16) | ((unsigned int)d << 24);
}

__device__ __forceinline__ uint4 pack8_bf16(float4 a, float4 b) {
    __nv_bfloat162 p0 = __floats2bfloat162_rn(a.x, a.y);
    __nv_bfloat162 p1 = __floats2bfloat162_rn(a.z, a.w);
    __nv_bfloat162 p2 = __floats2bfloat162_rn(b.x, b.y);
    __nv_bfloat162 p3 = __floats2bfloat162_rn(b.z, b.w);
    uint4 u;
    u.x = *(unsigned int*)&p0;
    u.y = *(unsigned int*)&p1;
    u.z = *(unsigned int*)&p2;
    u.w = *(unsigned int*)&p3;
    return u;
}

// ---------------------------------------------------------------------------
// K1: qv = x @ wqv_w^T + bias -> bf16  (2976 x 3072 x 128), tensor cores.
// ---------------------------------------------------------------------------
__global__ void __launch_bounds__(256) k_qv_mma(const float* __restrict__ x,
                                               const float* __restrict__ wq,
                                               const float* __restrict__ bias) {
    __shared__ __align__(16) unsigned char smem[32768];
    const int A_OFF = 0;
    const int B_OFF = 16384;
    int m0 = blockIdx.y * 128;
    int n0 = blockIdx.x * 128;
    int tid = threadIdx.x;
    int lane = tid & 31;
    int wid = tid >> 5;
    int mw = (wid >> 1) * 32;
    int nw = (wid & 1) * 64;
    unsigned int sbase = (unsigned int)__cvta_generic_to_shared(smem);
    float acc[2][8][4] = {};
    for (int kc = 0; kc < 128; kc += 64) {
        if (kc != 0) __syncthreads();
#pragma unroll
        for (int l = 0; l < 4; l++) {
            int e = tid + l * 256;
            int row = e >> 3;
            int ch = e & 7;
            int sw = ch ^ (row & 7);
            int gm = m0 + row;
            float4 a0 = make_float4(0.f, 0.f, 0.f, 0.f);
            float4 a1 = make_float4(0.f, 0.f, 0.f, 0.f);
            if (gm < BN_) {
                const float* src = x + (size_t)gm * 128 + kc + ch * 8;
                a0 = *(const float4*)src;
                a1 = *(const float4*)(src + 4);
            }
            *(uint4*)(smem + A_OFF + 16 * (row * 8 + sw)) = pack8_bf16(a0, a1);
            const float* srcb = wq + (size_t)(n0 + row) * 128 + kc + ch * 8;
            float4 b0 = *(const float4*)srcb;
            float4 b1 = *(const float4*)(srcb + 4);
            *(uint4*)(smem + B_OFF + 16 * (row * 8 + sw)) = pack8_bf16(b0, b1);
        }
        __syncthreads();
#pragma unroll
        for (int ks = 0; ks < 4; ks++) {
            int chb = 2 * ks + (lane >> 4);
            unsigned int afr[2][4];
#pragma unroll
            for (int ms = 0; ms < 2; ms++) {
                int row = mw + ms * 16 + (lane & 15);
                ldsm4(afr[ms], sbase + A_OFF + 16 * (row * 8 + (chb ^ (row & 7))));
            }
#pragma unroll
            for (int nsp = 0; nsp < 4; nsp++) {
                unsigned int bfr[4];
                int row = nw + nsp * 16 + (lane & 15);
                ldsm4(bfr, sbase + B_OFF + 16 * (row * 8 + (chb ^ (row & 7))));
#pragma unroll
                for (int ms = 0; ms < 2; ms++) {
                    mma16816(acc[ms][nsp * 2], afr[ms], bfr[0], bfr[2]);
                    mma16816(acc[ms][nsp * 2 + 1], afr[ms], bfr[1], bfr[3]);
                }
            }
        }
    }
#pragma unroll
    for (int ms = 0; ms < 2; ms++) {
        int gm0 = m0 + mw + ms * 16 + (lane >> 2);
        int gm1 = gm0 + 8;
#pragma unroll
        for (int ns = 0; ns < 8; ns++) {
            int col = n0 + nw + ns * 8 + (lane & 3) * 2;
            float2 bv = *(const float2*)&bias[col];
            if (gm0 < BN_) {
                __nv_bfloat162 o = __floats2bfloat162_rn(acc[ms][ns][0] + bv.x,
                                                         acc[ms][ns][1] + bv.y);
                *(__nv_bfloat162*)&g_qvh[(size_t)gm0 * C3_ + col] = o;
            }
            if (gm1 < BN_) {
                __nv_bfloat162 o = __floats2bfloat162_rn(acc[ms][ns][2] + bv.x,
                                                         acc[ms][ns][3] + bv.y);
                *(__nv_bfloat162*)&g_qvh[(size_t)gm1 * C3_ + col] = o;
            }
        }
    }
}

// ---------------------------------------------------------------------------
// K1b: quantize q (from g_qvh) and k = x*wk to biased-u8, once per (bh, s).
// ---------------------------------------------------------------------------
__global__ void __launch_bounds__(256) k_quant(const float* __restrict__ x,
                                               const float* __restrict__ wk) {
    int idx = blockIdx.x * 256 + threadIdx.x;
    int p = idx & 31;
    int rest = idx >> 5;
    int s = rest % NP_;
    int bh = rest / NP_;
    if (bh >= BH_) return;
    int b = bh >> 3, h = bh & 7;
    unsigned int qu = 0x80808080u;
    unsigned int ku = 0x80808080u;
    if (s < N_) {
        uint2 u2 = *(const uint2*)(g_qvh + (size_t)(b * N_ + s) * C3_ + h * 128 + p * 4);
        __nv_bfloat162 h0 = *(__nv_bfloat162*)&u2.x;
        __nv_bfloat162 h1 = *(__nv_bfloat162*)&u2.y;
        float4 qf = make_float4(__low2float(h0), __high2float(h0),
                                __low2float(h1), __high2float(h1));
        qu = quant4(qf);
        float4 xv = *(const float4*)&x[((size_t)(b * N_ + s)) * 128 + p * 4];
        float4 wv = *(const float4*)&wk[h * 128 + p * 4];
        float4 kf;
        kf.x = xv.x * wv.x;
        kf.y = xv.y * wv.y;
        kf.z = xv.z * wv.z;
        kf.w = xv.w * wv.w;
        ku = quant4(kf);
    }
    g_q8[((size_t)bh * NP_ + s) * 32 + p] = qu;
    g_k8[((size_t)bh * NP_ + s) * 32 + p] = ku;
}

// ---------------------------------------------------------------------------
// K2: E[i,j] = exp(-scale * sad(q8[i], k8[j])) -> bf16 padded.
// ---------------------------------------------------------------------------
__global__ void __launch_bounds__(256) k_scores() {
    __shared__ unsigned int q_sh[64][32];
    __shared__ unsigned int k_sh[64][32];
    __shared__ float part[16][64];
    int bh = blockIdx.z;
    int i0 = blockIdx.y * 64, j0 = blockIdx.x * 64;
    int tid = threadIdx.x;
    int cg = tid & 15, rg = tid >> 4;
    const unsigned int* q8 = g_q8 + (size_t)bh * NP_ * 32;
    const unsigned int* k8 = g_k8 + (size_t)bh * NP_ * 32;
#pragma unroll
    for (int l = 0; l < 4; l++) {
        int e = tid + l * 256;
        int v = e & 511;
        int row = v >> 3;
        int ch = v & 7;
        int sw = ch ^ ((row >> 2) & 7);
        if (e < 512) {
            uint4 u = *(const uint4*)(q8 + ((size_t)(i0 + row)) * 32 + ch * 4);
            *(uint4*)&q_sh[row][sw * 4] = u;
        } else {
            uint4 u = *(const uint4*)(k8 + ((size_t)(j0 + row)) * 32 + ch * 4);
            *(uint4*)&k_sh[row][sw * 4] = u;
        }
    }
    __syncthreads();
    unsigned int acc[4][4];
#pragma unroll
    for (int i = 0; i < 4; i++) {
#pragma unroll
        for (int j = 0; j < 4; j++) acc[i][j] = 0u;
    }
#pragma unroll
    for (int p4 = 0; p4 < 8; p4++) {
        uint4 qv[4];
        uint4 kv[4];
#pragma unroll
        for (int i = 0; i < 4; i++) {
            int row = rg * 4 + i;
            int ch = p4 ^ ((row >> 2) & 7);
            qv[i] = *(const uint4*)&q_sh[row][ch * 4];
        }
#pragma unroll
        for (int j = 0; j < 4; j++) {
            int row = cg * 4 + j;
            int ch = p4 ^ ((row >> 2) & 7);
            kv[j] = *(const uint4*)&k_sh[row][ch * 4];
        }
#pragma unroll
        for (int i = 0; i < 4; i++) {
#pragma unroll
            for (int j = 0; j < 4; j++) {
                unsigned int a = acc[i][j];
                a = sad4(qv[i].x, kv[j].x, a);
                a = sad4(qv[i].y, kv[j].y, a);
                a = sad4(qv[i].z, kv[j].z, a);
                a = sad4(qv[i].w, kv[j].w, a);
                acc[i][j] = a;
            }
        }
    }
    const float nfac = -3.5355339059e-4f;
    float csum[4] = {0.f, 0.f, 0.f, 0.f};
    __nv_bfloat16* Erow = g_Ebf + (size_t)bh * NP_ * NP_;
    int jc0 = j0 + cg * 4;
    bool cv = (jc0 < N_);
#pragma unroll
    for (int i = 0; i < 4; i++) {
        int gi = i0 + rg * 4 + i;
        bool valid = (gi < N_) && cv;
        float ev[4];
#pragma unroll
        for (int j = 0; j < 4; j++) {
            ev[j] = valid ? __expf(nfac * (float)acc[i][j]) : 0.f;
        }
        __nv_bfloat162 p0 = __floats2bfloat162_rn(ev[0], ev[1]);
        __nv_bfloat162 p1 = __floats2bfloat162_rn(ev[2], ev[3]);
        uint2 u;
        u.x = *(unsigned int*)&p0;
        u.y = *(unsigned int*)&p1;
        *(uint2*)&Erow[(size_t)gi * NP_ + jc0] = u;
        if (valid) {
#pragma unroll
            for (int j = 0; j < 4; j++) csum[j] += ev[j];
        }
    }
#pragma unroll
    for (int j = 0; j < 4; j++) part[rg][cg * 4 + j] = csum[j];
    __syncthreads();
    if (tid < 64) {
        int gj = j0 + tid;
        if (gj < N_) {
            float s = 0.f;
#pragma unroll
            for (int r = 0; r < 16; r++) s += part[r][tid];
            g_denpart[((size_t)blockIdx.y * BH_ + bh) * N_ + gj] = s;
        }
    }
}

// ---------------------------------------------------------------------------
// K3: reduce denominator partials -> rden = 1/(1 + colsum)
// ---------------------------------------------------------------------------
__global__ void k_rden() {
    int idx = blockIdx.x * blockDim.x + threadIdx.x;
    if (idx >= BH_ * N_) return;
    float s = 0.f;
#pragma unroll
    for (int t = 0; t < NT64; t++) {
        s += g_denpart[(size_t)t * BH_ * N_ + idx];
    }
    g_rden[idx] = 1.f / (1.f + s);
}

// ---------------------------------------------------------------------------
// K3b: vb*rden[s] -> bf16, padded rows zero
// ---------------------------------------------------------------------------
__global__ void __launch_bounds__(256) k_prep() {
    int idx = blockIdx.x * 256 + threadIdx.x;
    int wp = idx & 63;
    int rest = idx >> 6;
    int s = rest % NP_;
    int bh = rest / NP_;
    if (bh >= BH_) return;
    int b = bh >> 3, h = bh & 7;
    unsigned int ub = 0u;
    if (s < N_) {
        const __nv_bfloat16* vb = g_qvh + (size_t)(b * N_ + s) * C3_ + (16 + h) * 128 + wp * 2;
        unsigned int raw = *(const unsigned int*)vb;
        __nv_bfloat162 hv = *(__nv_bfloat162*)&raw;
        float r = g_rden[bh * N_ + s];
        __nv_bfloat162 o = __floats2bfloat162_rn(__low2float(hv) * r,
                                                 __high2float(hv) * r);
        ub = *(unsigned int*)&o;
    }
    *(unsigned int*)&g_vbb[((size_t)bh * NP_ + s) * W_ + wp * 2] = ub;
}

// ---------------------------------------------------------------------------
// K4: tensor-core attention apply, cp.async double-buffered pipeline.
//   acc1 = E^T @ vf  (scaled by rden[d] at epilogue)
//   acc2 = E @ (vb*rden[s])
// CTA: 64 d x 128 w, 8 warps, s-chunks of 64, 2-stage smem (2 x 48KB dynamic).
// minBlocks=2: two CTAs per SM (192KB smem), halves wave count + overlaps syncs.
// ---------------------------------------------------------------------------
__device__ __forceinline__ void av_issue(unsigned int sb, int s0, int d0, int tid,
                                         const __nv_bfloat16* Ebase,
                                         const __nv_bfloat16* Vfp,
                                         const __nv_bfloat16* Vbp) {
    const int ETR_OFF = 0;
    const int ED_OFF  = 8192;
    const int VF_OFF  = 16384;
    const int VB_OFF  = 32768;
#pragma unroll
    for (int l = 0; l < 2; l++) {
        int v = tid + l * 256;
        int row = v >> 3;
        int ch = v & 7;
        int sw = ch ^ (row & 7);
        cpa16(sb + ETR_OFF + 16 * (row * 8 + sw),
              Ebase + (size_t)(s0 + row) * NP_ + d0 + ch * 8);
        cpa16(sb + ED_OFF + 16 * (row * 8 + sw),
              Ebase + (size_t)(d0 + row) * NP_ + s0 + ch * 8);
    }
#pragma unroll
    for (int l = 0; l < 4; l++) {
        int v = tid + l * 256;
        int row = v >> 4;
        int ch = v & 15;
        int sw = ch ^ (row & 7);
        int gs = s0 + row;
        int szf = (gs < N_) ? 16 : 0;
        cpa16z(sb + VF_OFF + 16 * (row * 16 + sw),
               Vfp + (size_t)gs * C3_ + ch * 8, szf);
        cpa16(sb + VB_OFF + 16 * (row * 16 + sw),
              Vbp + (size_t)gs * W_ + ch * 8);
    }
}

__global__ void __launch_bounds__(256, 2) k_av_mma() {
    extern __shared__ __align__(16) unsigned char smem[];
    const int STAGE  = 49152;
    const int ETR_OFF = 0;
    const int ED_OFF  = 8192;
    const int VF_OFF  = 16384;
    const int VB_OFF  = 32768;

    int d0 = blockIdx.x * 64;
    int b = blockIdx.y;
    int h = blockIdx.z;
    int bh = b * 8 + h;
    int tid = threadIdx.x;
    int lane = tid & 31;
    int wid = tid >> 5;
    int dw = (wid >> 1) * 16;
    int n0 = (wid & 1) * 64;

    const __nv_bfloat16* Ebase = g_Ebf + (size_t)bh * NP_ * NP_;
    const __nv_bfloat16* Vfp = g_qvh + (size_t)b * N_ * C3_ + (8 + h) * 128;
    const __nv_bfloat16* Vbp = g_vbb + (size_t)bh * NP_ * W_;

    unsigned int sbase = (unsigned int)__cvta_generic_to_shared(smem);

    float acc1[8][4];
    float acc2[8][4];
#pragma unroll
    for (int i = 0; i < 8; i++) {
#pragma unroll
        for (int j = 0; j < 4; j++) {
            acc1[i][j] = 0.f;
            acc2[i][j] = 0.f;
        }
    }

    // prologue: chunk 0 into stage 0
    av_issue(sbase, 0, d0, tid, Ebase, Vfp, Vbp);
    CP_COMMIT();

    for (int st = 0; st < NP_ / 64; st++) {
        unsigned int sb = sbase + (unsigned int)(st & 1) * STAGE;
        if (st + 1 < NP_ / 64) {
            av_issue(sbase + (unsigned int)((st + 1) & 1) * STAGE,
                     (st + 1) * 64, d0, tid, Ebase, Vfp, Vbp);
            CP_COMMIT();
            CP_WAIT(1);
        } else {
            CP_WAIT(0);
        }
        __syncthreads();
#pragma unroll
        for (int ks = 0; ks < 4; ks++) {
            int k0 = ks * 16;
            unsigned int a1[4];
            unsigned int a2[4];
            int srow = k0 + (lane & 7) + ((lane >> 4) & 1) * 8;
            int sch = (dw >> 3) + ((lane >> 3) & 1);
            ldsm4t(a1, sb + ETR_OFF + 16 * (srow * 8 + (sch ^ (srow & 7))));
            int drow = dw + (lane & 15);
            int dch = (k0 >> 3) + (lane >> 4);
            ldsm4(a2, sb + ED_OFF + 16 * (drow * 8 + (dch ^ (drow & 7))));
            int krow = k0 + (lane & 7) + ((lane >> 3) & 1) * 8;
            int kx = krow & 7;
#pragma unroll
            for (int nt2 = 0; nt2 < 4; nt2++) {
                int ch = ((n0 + nt2 * 16) >> 3) + (lane >> 4);
                unsigned int rbf[4];
                unsigned int rbb[4];
                ldsm4t(rbf, sb + VF_OFF + 16 * (krow * 16 + (ch ^ kx)));
                ldsm4t(rbb, sb + VB_OFF + 16 * (krow * 16 + (ch ^ kx)));
                mma16816(acc1[nt2 * 2], a1, rbf[0], rbf[1]);
                mma16816(acc1[nt2 * 2 + 1], a1, rbf[2], rbf[3]);
                mma16816(acc2[nt2 * 2], a2, rbb[0], rbb[1]);
                mma16816(acc2[nt2 * 2 + 1], a2, rbb[2], rbb[3]);
            }
        }
        __syncthreads();
    }
    // epilogue: y = rden[d]*acc1 + acc2  -> bf16
    int r0 = d0 + dw + (lane >> 2);
    int r1 = r0 + 8;
    const float* rden = g_rden + (size_t)bh * N_;
    float rd0 = (r0 < N_) ? rden[r0] : 0.f;
    float rd1 = (r1 < N_) ? rden[r1] : 0.f;
    __nv_bfloat16* yb = g_yhh + (size_t)h * BN_ * W_ + (size_t)b * N_ * W_;
#pragma unroll
    for (int nt = 0; nt < 8; nt++) {
        int col = n0 + nt * 8 + (lane & 3) * 2;
        if (r0 < N_) {
            __nv_bfloat162 o0 = __floats2bfloat162_rn(
                rd0 * acc1[nt][0] + acc2[nt][0],
                rd0 * acc1[nt][1] + acc2[nt][1]);
            *(__nv_bfloat162*)&yb[(size_t)r0 * W_ + col] = o0;
        }
        if (r1 < N_) {
            __nv_bfloat162 o1 = __floats2bfloat162_rn(
                rd1 * acc1[nt][2] + acc2[nt][2],
                rd1 * acc1[nt][3] + acc2[nt][3]);
            *(__nv_bfloat162*)&yb[(size_t)r1 * W_ + col] = o1;
        }
    }
}

// ---------------------------------------------------------------------------
// K5: y = sum_h y_h; y = qgelu(y + 4.5) - 4.5; out = x + y @ fanin_w^T + fb
// ---------------------------------------------------------------------------
__device__ __forceinline__ float qact(float v) {
    float z = v + 4.5f;
    return z / (1.f + __expf(-1.702f * z)) - 4.5f;
}

__global__ void __launch_bounds__(256) k_final(const float* __restrict__ x,
                                               const float* __restrict__ fw,
                                               const float* __restrict__ fbias,
                                               float* __restrict__ out) {
    __shared__ float ag[32][128];
    __shared__ float bt[128][33];
    int m0 = blockIdx.x * 32;
    int tid = threadIdx.x;
    int cq = tid & 31, rg = tid >> 5;
#pragma unroll
    for (int l = 0; l < 4; l++) {
        int e = tid + l * 256;
        int r = e >> 5;
        int wi = (e & 31) * 4;
        float4 s = make_float4(0.f, 0.f, 0.f, 0.f);
#pragma unroll
        for (int hh = 0; hh < H_; hh++) {
            uint2 u = *(const uint2*)&g_yhh[((size_t)hh * BN_ + m0 + r) * 128 + wi];
            __nv_bfloat162 h0 = *(__nv_bfloat162*)&u.x;
            __nv_bfloat162 h1 = *(__nv_bfloat162*)&u.y;
            s.x += __low2float(h0);
            s.y += __high2float(h0);
            s.z += __low2float(h1);
            s.w += __high2float(h1);
        }
        float4 a;
        a.x = qact(s.x); a.y = qact(s.y); a.z = qact(s.z); a.w = qact(s.w);
        *(float4*)&ag[r][wi] = a;
    }
    float acc[4][4] = {};
    for (int k0 = 0; k0 < 128; k0 += 32) {
#pragma unroll
        for (int l = 0; l < 16; l++) {
            int e = tid + l * 256;
            int c = e >> 5;
            int kk = e & 31;
            bt[c][kk] = fw[(size_t)c * 128 + k0 + kk];
        }
        __syncthreads();
#pragma unroll
        for (int kk = 0; kk < 32; kk++) {
            float av[4];
            float bv[4];
#pragma unroll
            for (int i = 0; i < 4; i++) av[i] = ag[rg * 4 + i][k0 + kk];
#pragma unroll
            for (int j = 0; j < 4; j++) bv[j] = bt[cq * 4 + j][kk];
#pragma unroll
            for (int i = 0; i < 4; i++) {
#pragma unroll
                for (int j = 0; j < 4; j++) {
                    acc[i][j] += av[i] * bv[j];
                }
            }
        }
        __syncthreads();
    }
    int c0 = cq * 4;
    float4 fb4 = *(const float4*)&fbias[c0];
#pragma unroll
    for (int i = 0; i < 4; i++) {
        int row = m0 + rg * 4 + i;
        float4 xr = *(const float4*)&x[(size_t)row * 128 + c0];
        float4 o;
        o.x = xr.x + acc[i][0] + fb4.x;
        o.y = xr.y + acc[i][1] + fb4.y;
        o.z = xr.z + acc[i][2] + fb4.z;
        o.w = xr.w + acc[i][3] + fb4.w;
        *(float4*)&out[(size_t)row * 128 + c0] = o;
    }
}

// ---------------------------------------------------------------------------
extern "C" void kernel_launch(void* const* d_in, const int* in_sizes, int n_in,
                              void* d_out, int out_size) {
    (void)in_sizes; (void)n_in; (void)out_size;
    const float* x       = (const float*)d_in[0];
    const float* wk      = (const float*)d_in[1];
    const float* wqv_w   = (const float*)d_in[2];
    const float* wqv_b   = (const float*)d_in[3];
    const float* fanin_w = (const float*)d_in[4];
    const float* fanin_b = (const float*)d_in[5];
    float* out = (float*)d_out;

    cudaFuncSetAttribute(k_av_mma,
                         cudaFuncAttributeMaxDynamicSharedMemorySize, 98304);

    k_qv_mma<<<dim3(C3_ / 128, (BN_ + 127) / 128), 256>>>(x, wqv_w, wqv_b);
    k_quant<<<(BH_ * NP_ * 32) / 256, 256>>>(x, wk);
    k_scores<<<dim3(NT64, NT64, BH_), 256>>>();
    k_rden<<<(BH_ * N_ + 255) / 256, 256>>>();
    k_prep<<<(BH_ * NP_ * 64) / 256, 256>>>();
    k_av_mma<<<dim3(NP_ / 64, B_, H_), 256, 98304>>>();
    k_final<<<BN_ / 32, 256>>>(x, fanin_w, fanin_b, out);
}